// round 15
// baseline (speedup 1.0000x reference)
#include <cuda_runtime.h>
#include <cuda_bf16.h>
#include <math.h>
#include <stdint.h>

#define LTOK 65536
#define CDIM 192
#define HIDD 768

typedef unsigned long long ull;
typedef unsigned int u32;

// ---------------- scratch (static device globals; no allocation) ----------------
__device__ __nv_bfloat16 g_xwb[LTOK * CDIM];   // LN1 out (window order) / LN2 out (token order)
__device__ __nv_bfloat16 g_q[LTOK * CDIM];     // [win,head,n,d] bf16 (q pre-scaled)
__device__ __nv_bfloat16 g_k[LTOK * CDIM];
__device__ __nv_bfloat16 g_v[LTOK * CDIM];
__device__ __nv_bfloat16 g_aob[LTOK * CDIM];   // attention out, window order, bf16
__device__ float g_xr[LTOK * CDIM];            // first residual, token order, fp32
__device__ __nv_bfloat16 g_hb[LTOK * HIDD];    // MLP hidden, bf16
__device__ __nv_bfloat16 g_bias6b[6 * 256 * 256];   // rel-pos bias, bf16
// transposed bf16 weights: [N, K] row-major
__device__ __nv_bfloat16 g_wqkv[576 * 192];
__device__ __nv_bfloat16 g_wproj[192 * 192];
__device__ __nv_bfloat16 g_wfc1[768 * 192];
__device__ __nv_bfloat16 g_wfc2[192 * 768];

// ---------------- mma.sync helpers ----------------
__device__ __forceinline__ u32 smem_u32(const void* p) {
    u32 a;
    asm("{ .reg .u64 t; cvta.to.shared.u64 t, %1; cvt.u32.u64 %0, t; }" : "=r"(a) : "l"(p));
    return a;
}
#define LDM4(R, addr)                                                            \
    asm volatile("ldmatrix.sync.aligned.m8n8.x4.shared.b16 {%0,%1,%2,%3}, [%4];" \
        : "=r"((R)[0]), "=r"((R)[1]), "=r"((R)[2]), "=r"((R)[3]) : "r"(addr))

#define LDM4T(R, addr)                                                           \
    asm volatile("ldmatrix.sync.aligned.m8n8.x4.trans.shared.b16 {%0,%1,%2,%3}, [%4];" \
        : "=r"((R)[0]), "=r"((R)[1]), "=r"((R)[2]), "=r"((R)[3]) : "r"(addr))

#define MMA(dd, A, B0, B1)                                                       \
    asm volatile("mma.sync.aligned.m16n8k16.row.col.f32.bf16.bf16.f32 "          \
        "{%0,%1,%2,%3}, {%4,%5,%6,%7}, {%8,%9}, {%0,%1,%2,%3};"                  \
        : "+f"((dd)[0]), "+f"((dd)[1]), "+f"((dd)[2]), "+f"((dd)[3])             \
        : "r"((A)[0]), "r"((A)[1]), "r"((A)[2]), "r"((A)[3]), "r"(B0), "r"(B1))

__device__ __forceinline__ u32 bfpack(float a, float b) {
    __nv_bfloat162 h = __floats2bfloat162_rn(a, b);
    return *(u32*)&h;
}

__device__ __forceinline__ float gelu_exact(float x) {
    return 0.5f * x * (1.0f + erff(x * 0.70710678118654752f));
}

// ============ coalesced tiled weight transpose: Wt[n*K+k] = W[k*N+n] ============
__global__ __launch_bounds__(256) void transw_tiled(const float* __restrict__ qkvw,
                                                    const float* __restrict__ projw,
                                                    const float* __restrict__ fc1w,
                                                    const float* __restrict__ fc2w) {
    __shared__ float t[32][33];
    int b = blockIdx.x;
    const float* W; __nv_bfloat16* Wt; int K, N, tb;
    if (b < 108)      { W = qkvw;  Wt = g_wqkv;  K = 192; N = 576; tb = b; }
    else if (b < 144) { W = projw; Wt = g_wproj; K = 192; N = 192; tb = b - 108; }
    else if (b < 288) { W = fc1w;  Wt = g_wfc1;  K = 192; N = 768; tb = b - 144; }
    else              { W = fc2w;  Wt = g_wfc2;  K = 768; N = 192; tb = b - 288; }
    int ntiles = N >> 5;
    int tr = tb / ntiles, tc = tb - tr * ntiles;   // k-tile, n-tile
    int tx = threadIdx.x & 31, ty = threadIdx.x >> 5;
#pragma unroll
    for (int rr = 0; rr < 4; rr++) {
        int k = tr * 32 + ty + rr * 8;
        t[ty + rr * 8][tx] = W[(size_t)k * N + tc * 32 + tx];
    }
    __syncthreads();
#pragma unroll
    for (int rr = 0; rr < 4; rr++) {
        int n = tc * 32 + ty + rr * 8;
        Wt[(size_t)n * K + tr * 32 + tx] = __float2bfloat16_rn(t[tx][ty + rr * 8]);
    }
}

// ============ relative position bias gather (bf16) ============
__global__ void bias6_kernel(const int* __restrict__ rpi, const float* __restrict__ rpb) {
    int id = blockIdx.x * 256 + threadIdx.x;
    int head = id >> 16;
    int nm = id & 65535;
    g_bias6b[id] = __float2bfloat16_rn(rpb[rpi[nm] * 6 + head]);
}

// ============ LayerNorm: warp-per-token, bf16 out ============
__global__ __launch_bounds__(256) void ln_kernel(const float* __restrict__ xin,
                                                 const float* __restrict__ gw,
                                                 const float* __restrict__ bw, int mode) {
    int gwid = (blockIdx.x * 256 + threadIdx.x) >> 5;
    int l = threadIdx.x & 31;
    int nwarp = (gridDim.x * 256) >> 5;

    float gg[6], bb[6];
#pragma unroll
    for (int j = 0; j < 6; j++) { gg[j] = gw[l + 32 * j]; bb[j] = bw[l + 32 * j]; }

    const float* src = mode ? xin : g_xr;
    for (int s = gwid; s < LTOK; s += nwarp) {
        const float* in = src + (size_t)s * CDIM;
        float v[6], sum = 0.0f, sq = 0.0f;
#pragma unroll
        for (int j = 0; j < 6; j++) {
            v[j] = in[l + 32 * j];
            sum += v[j];
            sq += v[j] * v[j];
        }
#pragma unroll
        for (int o = 16; o; o >>= 1) {
            sum += __shfl_xor_sync(0xffffffffu, sum, o);
            sq  += __shfl_xor_sync(0xffffffffu, sq, o);
        }
        float mean = sum * (1.0f / CDIM);
        float var = sq * (1.0f / CDIM) - mean * mean;
        float rs = rsqrtf(var + 1e-5f);
        int r;
        if (mode) {
            int h = s >> 8, w = s & 255;
            int i = (h + 248) & 255, j = (w + 248) & 255;
            r = (((i >> 4) << 4) + (j >> 4)) * 256 + ((i & 15) << 4) + (j & 15);
        } else {
            r = s;
        }
        __nv_bfloat16* dst = g_xwb + (size_t)r * CDIM;
#pragma unroll
        for (int j = 0; j < 6; j++)
            dst[l + 32 * j] = __float2bfloat16_rn((v[j] - mean) * rs * gg[j] + bb[j]);
    }
}

// ============ epilogue pair-store ============
template <int MODE>
__device__ __forceinline__ void store2(int r, int n, float2 v,
                                       const float* __restrict__ aux,
                                       float* __restrict__ outp) {
    if (MODE == 0) {
        int which = n / 192;
        int rem = n - which * 192;
        int head = rem >> 5, dd = rem & 31;
        int wnd = r >> 8, nn = r & 255;
        __nv_bfloat16* dst = ((which == 0) ? g_q : (which == 1) ? g_k : g_v)
                             + (size_t)((wnd * 6 + head) * 256 + nn) * 32 + dd;
        if (which == 0) {
            v.x *= 0.17677669529663687f;
            v.y *= 0.17677669529663687f;
        }
        *(u32*)dst = bfpack(v.x, v.y);
    } else if (MODE == 1) {
        int wnd = r >> 8, nn = r & 255;
        int i_ = ((wnd >> 4) << 4) + (nn >> 4);
        int j_ = ((wnd & 15) << 4) + (nn & 15);
        int s = (((i_ + 8) & 255) << 8) + ((j_ + 8) & 255);
        float2 a = *(const float2*)(aux + (size_t)s * CDIM + n);
        v.x += a.x; v.y += a.y;
        *(float2*)(g_xr + (size_t)s * CDIM + n) = v;
    } else if (MODE == 2) {
        *(u32*)(g_hb + (size_t)r * HIDD + n) = bfpack(gelu_exact(v.x), gelu_exact(v.y));
    } else {
        float2 a = *(const float2*)(g_xr + (size_t)r * CDIM + n);
        v.x += a.x; v.y += a.y;
        *(float2*)(outp + (size_t)r * CDIM + n) = v;
    }
}

// ============ A-resident GEMM, K=192: A in smem, B-frags via direct LDG ============
// B (weights) is L2-resident and laid out [N,K] row-major == exact mma.sync b-frag
// source: lane l reads u32 at W[n + l/4][k + (l%4)*2] and +8. No B smem, no syncs
// in the n-loop, 2 CTAs/SM.
#define ARES_SMEM (128 * 400)
template <int MODE>
__global__ __launch_bounds__(256, 2) void tmmaA(const float* __restrict__ bias,
                                                const float* __restrict__ aux,
                                                float* __restrict__ outp, int NT) {
    extern __shared__ __align__(16) char sm[];
    char* As = sm;                       // 128 * 400

    const __nv_bfloat16* Ag = (MODE == 1) ? g_aob : g_xwb;
    const __nv_bfloat16* Wt = (MODE == 0) ? g_wqkv : (MODE == 1) ? g_wproj : g_wfc1;

    int tid = threadIdx.x;
    int w = tid >> 5, l = tid & 31;
    int wm = w & 3, wn = w >> 2;
    int m0 = blockIdx.x * 128;

    // load A tile (coalesced), once
#pragma unroll
    for (int j = 0; j < 12; j++) {
        int id = tid + j * 256;
        int row = id / 24, ch = id - row * 24;
        *(uint4*)(As + row * 400 + ch * 16) =
            *(const uint4*)(Ag + (size_t)(m0 + row) * 192 + ch * 8);
    }
    __syncthreads();

    u32 sa = smem_u32(As);
    u32 aBase0 = sa + (wm * 32 + (l & 15)) * 400 + (l >> 4) * 16;        // mt=0
    u32 aBase1 = aBase0 + 16 * 400;                                      // mt=1

    // per-lane B base: row n = wn*32 + l/4 (+ j*8 + nt*64), col k = (l%4)*2 (+ ks*16)
    const __nv_bfloat16* Brow = Wt + (size_t)(wn * 32 + (l >> 2)) * 192 + (l & 3) * 2;
    int lq = l >> 2, lr = l & 3;

    for (int nt = 0; nt < NT; nt++) {
        const __nv_bfloat16* Wn = Brow + (size_t)nt * 64 * 192;
        float d[2][4][4];
#pragma unroll
        for (int mt = 0; mt < 2; mt++)
#pragma unroll
            for (int nj = 0; nj < 4; nj++)
#pragma unroll
                for (int q = 0; q < 4; q++) d[mt][nj][q] = 0.0f;

#pragma unroll
        for (int ks = 0; ks < 12; ks++) {
            u32 a0[4], a1[4];
            LDM4(a0, aBase0 + ks * 32);
            LDM4(a1, aBase1 + ks * 32);
#pragma unroll
            for (int j = 0; j < 4; j++) {
                const __nv_bfloat16* bp = Wn + j * 8 * 192 + ks * 16;
                u32 b0 = *(const u32*)bp;
                u32 b1 = *(const u32*)(bp + 8);
                MMA(d[0][j], a0, b0, b1);
                MMA(d[1][j], a1, b0, b1);
            }
        }
        // epilogue
#pragma unroll
        for (int mt = 0; mt < 2; mt++) {
            int ra = m0 + wm * 32 + mt * 16 + lq;
            int rb = ra + 8;
#pragma unroll
            for (int nj = 0; nj < 4; nj++) {
                int ng = nt * 64 + wn * 32 + nj * 8 + lr * 2;
                float2 b2 = *(const float2*)(bias + ng);
                float2 v0 = make_float2(d[mt][nj][0] + b2.x, d[mt][nj][1] + b2.y);
                float2 v1 = make_float2(d[mt][nj][2] + b2.x, d[mt][nj][3] + b2.y);
                store2<MODE>(ra, ng, v0, aux, outp);
                store2<MODE>(rb, ng, v1, aux, outp);
            }
        }
    }
}

// ============ fc2 GEMM: K=768, BM=128, BN=192; A double-buffered, B via LDG ============
#define FC2_SMEM (2 * 128 * 80)
__global__ __launch_bounds__(256) void tmmaF(const float* __restrict__ bias,
                                             float* __restrict__ outp) {
    extern __shared__ __align__(16) char smF[];
    int tid = threadIdx.x;
    int w = tid >> 5, l = tid & 31;
    int wm = w & 3, wn = w >> 2;   // 4 x 2 warps; warp tile 32 x 96
    int m0 = blockIdx.x * 128;

    const __nv_bfloat16* Ag = g_hb;
    const __nv_bfloat16* Brow = g_wfc2 + (size_t)(wn * 96 + (l >> 2)) * 768 + (l & 3) * 2;

    u32 s0 = smem_u32(smF);
    u32 aOff = (wm * 32 + (l & 7) + ((l >> 3) & 1) * 8) * 80 + (l >> 4) * 16;

    float d[2][12][4];
#pragma unroll
    for (int mt = 0; mt < 2; mt++)
#pragma unroll
        for (int nj = 0; nj < 12; nj++)
#pragma unroll
            for (int q = 0; q < 4; q++) d[mt][nj][q] = 0.0f;

    uint4 pa[2];
#pragma unroll
    for (int j = 0; j < 2; j++) {
        int id = tid + j * 256;
        pa[j] = *(const uint4*)(Ag + (size_t)(m0 + (id >> 2)) * HIDD + (id & 3) * 8);
    }
    // store k-slab 0 into buffer 0
#pragma unroll
    for (int j = 0; j < 2; j++) {
        int id = tid + j * 256;
        *(uint4*)(smF + (id >> 2) * 80 + (id & 3) * 16) = pa[j];
    }
    __syncthreads();
    // prefetch slab 1
#pragma unroll
    for (int j = 0; j < 2; j++) {
        int id = tid + j * 256;
        pa[j] = *(const uint4*)(Ag + (size_t)(m0 + (id >> 2)) * HIDD + 32 + (id & 3) * 8);
    }

    for (int kt = 0; kt < 24; kt++) {
        int cur = kt & 1;
        // 1. store prefetched slab kt+1 into alt buffer
        if (kt + 1 < 24) {
            char* base = smF + (1 - cur) * 10240;
#pragma unroll
            for (int j = 0; j < 2; j++) {
                int id = tid + j * 256;
                *(uint4*)(base + (id >> 2) * 80 + (id & 3) * 16) = pa[j];
            }
        }
        // 2. prefetch slab kt+2
        if (kt + 2 < 24) {
            int kc = (kt + 2) * 32;
#pragma unroll
            for (int j = 0; j < 2; j++) {
                int id = tid + j * 256;
                pa[j] = *(const uint4*)(Ag + (size_t)(m0 + (id >> 2)) * HIDD + kc + (id & 3) * 8);
            }
        }
        // 3. MMAs: A from smem, B-frags via LDG
        u32 aBase = s0 + cur * 10240 + aOff;
#pragma unroll
        for (int ks = 0; ks < 2; ks++) {
            u32 a0[4], a1[4];
            LDM4(a0, aBase + ks * 32);
            LDM4(a1, aBase + 1280 + ks * 32);
            const __nv_bfloat16* Bk = Brow + kt * 32 + ks * 16;
#pragma unroll
            for (int g = 0; g < 6; g++) {
#pragma unroll
                for (int h2 = 0; h2 < 2; h2++) {
                    const __nv_bfloat16* bp = Bk + (size_t)(g * 16 + h2 * 8) * 768;
                    u32 b0 = *(const u32*)bp;
                    u32 b1 = *(const u32*)(bp + 8);
                    MMA(d[0][2 * g + h2], a0, b0, b1);
                    MMA(d[1][2 * g + h2], a1, b0, b1);
                }
            }
        }
        __syncthreads();
    }

    int lq = l >> 2, lr = l & 3;
#pragma unroll
    for (int mt = 0; mt < 2; mt++) {
        int ra = m0 + wm * 32 + mt * 16 + lq;
        int rb = ra + 8;
#pragma unroll
        for (int nj = 0; nj < 12; nj++) {
            int ng = wn * 96 + nj * 8 + lr * 2;
            float2 b2 = *(const float2*)(bias + ng);
            float2 v0 = make_float2(d[mt][nj][0] + b2.x, d[mt][nj][1] + b2.y);
            float2 v1 = make_float2(d[mt][nj][2] + b2.x, d[mt][nj][3] + b2.y);
            store2<3>(ra, ng, v0, nullptr, outp);
            store2<3>(rb, ng, v1, nullptr, outp);
        }
    }
}

// ============ tensor-core attention: one block per (window, head) ============
#define ATT_SMEM (256 * 80 * 3)
__global__ __launch_bounds__(256, 2) void attn_mma(const float* __restrict__ mask) {
    extern __shared__ __align__(16) char sm[];
    char* Qs = sm;
    char* Ksm = sm + 256 * 80;
    char* Vsm = sm + 2 * 256 * 80;

    int bid = blockIdx.x;
    int wnd = bid / 6;
    int head = bid - wnd * 6;
    int tid = threadIdx.x;

    size_t gbase = (size_t)((wnd * 6 + head) * 256) * 32;
    const uint4* Qg = (const uint4*)(g_q + gbase);
    const uint4* Kg = (const uint4*)(g_k + gbase);
    const uint4* Vg = (const uint4*)(g_v + gbase);
    for (int i = tid; i < 1024; i += 256) {
        int row = i >> 2, c4 = i & 3;
        int off = row * 80 + c4 * 16;
        *(uint4*)(Qs + off)  = Qg[i];
        *(uint4*)(Ksm + off) = Kg[i];
        *(uint4*)(Vsm + off) = Vg[i];
    }
    __syncthreads();

    int w = tid >> 5, l = tid & 31;
    u32 sQ = smem_u32(Qs), sK = smem_u32(Ksm), sV = smem_u32(Vsm);
    bool border = ((wnd >> 4) == 15) || ((wnd & 15) == 15);

#pragma unroll 1
    for (int hh = 0; hh < 2; hh++) {
        int qr = hh * 128 + w * 16;
        u32 qa[8];
        LDM4(qa,     sQ + (qr + (l & 15)) * 80 + (l >> 4) * 16);
        LDM4(qa + 4, sQ + (qr + (l & 15)) * 80 + 32 + (l >> 4) * 16);

        int r0 = qr + (l >> 2);
        const __nv_bfloat16* bA = g_bias6b + head * 65536 + r0 * 256;
        const __nv_bfloat16* bB = bA + 2048;
        const float* mA = mask + (size_t)wnd * 65536 + r0 * 256;
        const float* mB = mA + 2048;

        float sA = 0.0f, sB = 0.0f;
        float o[4][4];
#pragma unroll
        for (int nt = 0; nt < 4; nt++)
#pragma unroll
            for (int q = 0; q < 4; q++) o[nt][q] = 0.0f;

#pragma unroll 1
        for (int kh = 0; kh < 2; kh++) {
            int kb0 = kh * 128;
            float d[16][4];
#pragma unroll
            for (int t = 0; t < 16; t++)
#pragma unroll
                for (int q = 0; q < 4; q++) d[t][q] = 0.0f;

#pragma unroll
            for (int t = 0; t < 16; t++) {
                u32 kb[4];
                LDM4(kb, sK + (kb0 + t * 8 + (l & 7)) * 80 + (l >> 3) * 16);
                MMA(d[t], qa, kb[0], kb[1]);
                MMA(d[t], qa + 4, kb[2], kb[3]);
            }

            u32 pbf[8][4];
#pragma unroll
            for (int t = 0; t < 16; t++) {
                int c = kb0 + t * 8 + 2 * (l & 3);
                float2 aA = __bfloat1622float2(*(const __nv_bfloat162*)(bA + c));
                float2 aB = __bfloat1622float2(*(const __nv_bfloat162*)(bB + c));
                if (border) {
                    float2 ma = *(const float2*)(mA + c);
                    float2 mb = *(const float2*)(mB + c);
                    aA.x += ma.x; aA.y += ma.y;
                    aB.x += mb.x; aB.y += mb.y;
                }
                float p0 = __expf(d[t][0] + aA.x);
                float p1 = __expf(d[t][1] + aA.y);
                float p2 = __expf(d[t][2] + aB.x);
                float p3 = __expf(d[t][3] + aB.y);
                sA += p0 + p1;
                sB += p2 + p3;
                int kt = t >> 1, s4 = (t & 1) * 2;
                pbf[kt][s4]     = bfpack(p0, p1);
                pbf[kt][s4 + 1] = bfpack(p2, p3);
            }

#pragma unroll
            for (int kt = 0; kt < 8; kt++) {
                u32 v0[4], v1[4];
                u32 vaddr = sV + (kb0 + kt * 16 + (l & 7) + ((l >> 3) & 1) * 8) * 80 + (l >> 4) * 16;
                LDM4T(v0, vaddr);
                LDM4T(v1, vaddr + 32);
                MMA(o[0], pbf[kt], v0[0], v0[1]);
                MMA(o[1], pbf[kt], v0[2], v0[3]);
                MMA(o[2], pbf[kt], v1[0], v1[1]);
                MMA(o[3], pbf[kt], v1[2], v1[3]);
            }
        }

        sA += __shfl_xor_sync(0xffffffffu, sA, 1);
        sA += __shfl_xor_sync(0xffffffffu, sA, 2);
        sB += __shfl_xor_sync(0xffffffffu, sB, 1);
        sB += __shfl_xor_sync(0xffffffffu, sB, 2);
        float invA = 1.0f / sA, invB = 1.0f / sB;

        __nv_bfloat16* OA = g_aob + (size_t)(wnd * 256 + r0) * CDIM + head * 32;
        __nv_bfloat16* OB = OA + (size_t)8 * CDIM;
#pragma unroll
        for (int nt = 0; nt < 4; nt++) {
            int c = nt * 8 + 2 * (l & 3);
            *(u32*)(OA + c) = bfpack(o[nt][0] * invA, o[nt][1] * invA);
            *(u32*)(OB + c) = bfpack(o[nt][2] * invB, o[nt][3] * invB);
        }
    }
}

// ============ host launcher ============
extern "C" void kernel_launch(void* const* d_in, const int* in_sizes, int n_in,
                              void* d_out, int out_size) {
    const float* x     = (const float*)d_in[0];
    const int*   rpi   = (const int*)d_in[1];
    const float* mask  = (const float*)d_in[2];
    const float* n1g   = (const float*)d_in[3];
    const float* n1b   = (const float*)d_in[4];
    const float* qkvw  = (const float*)d_in[5];
    const float* qkvb  = (const float*)d_in[6];
    const float* rpb   = (const float*)d_in[7];
    const float* projw = (const float*)d_in[8];
    const float* projb = (const float*)d_in[9];
    const float* n2g   = (const float*)d_in[10];
    const float* n2b   = (const float*)d_in[11];
    const float* fc1w  = (const float*)d_in[12];
    const float* fc1b  = (const float*)d_in[13];
    const float* fc2w  = (const float*)d_in[14];
    const float* fc2b  = (const float*)d_in[15];
    float* out = (float*)d_out;

    cudaFuncSetAttribute(attn_mma, cudaFuncAttributeMaxDynamicSharedMemorySize, ATT_SMEM);
    cudaFuncSetAttribute(tmmaA<0>, cudaFuncAttributeMaxDynamicSharedMemorySize, ARES_SMEM);
    cudaFuncSetAttribute(tmmaA<1>, cudaFuncAttributeMaxDynamicSharedMemorySize, ARES_SMEM);
    cudaFuncSetAttribute(tmmaA<2>, cudaFuncAttributeMaxDynamicSharedMemorySize, ARES_SMEM);
    cudaFuncSetAttribute(tmmaF, cudaFuncAttributeMaxDynamicSharedMemorySize, FC2_SMEM);

    transw_tiled<<<432, 256>>>(qkvw, projw, fc1w, fc2w);
    bias6_kernel<<<1536, 256>>>(rpi, rpb);

    ln_kernel<<<512, 256>>>(x, n1g, n1b, 1);                            // LN1 + shift + partition
    tmmaA<0><<<512, 256, ARES_SMEM>>>(qkvb, nullptr, nullptr, 9);       // QKV -> q/k/v bf16
    attn_mma<<<1536, 256, ATT_SMEM>>>(mask);                            // attention -> g_aob
    tmmaA<1><<<512, 256, ARES_SMEM>>>(projb, x, nullptr, 3);            // proj + reverse + resid
    ln_kernel<<<512, 256>>>(x, n2g, n2b, 0);                            // LN2 (reads g_xr)
    tmmaA<2><<<512, 256, ARES_SMEM>>>(fc1b, nullptr, nullptr, 12);      // fc1 + GELU -> g_hb
    tmmaF<<<512, 256, FC2_SMEM>>>(fc2b, out);                           // fc2 + resid -> out
}

// round 16
// speedup vs baseline: 2.2014x; 2.2014x over previous
#include <cuda_runtime.h>
#include <cuda_bf16.h>
#include <math.h>
#include <stdint.h>

#define LTOK 65536
#define CDIM 192
#define HIDD 768

typedef unsigned long long ull;
typedef unsigned int u32;

// ---------------- scratch (static device globals; no allocation) ----------------
__device__ __nv_bfloat16 g_xwb[LTOK * CDIM];   // LN1 out (window order) / LN2 out (token order)
__device__ __nv_bfloat16 g_q[LTOK * CDIM];     // [win,head,n,d] bf16 (q pre-scaled)
__device__ __nv_bfloat16 g_k[LTOK * CDIM];
__device__ __nv_bfloat16 g_v[LTOK * CDIM];
__device__ __nv_bfloat16 g_aob[LTOK * CDIM];   // attention out, window order, bf16
__device__ float g_xr[LTOK * CDIM];            // first residual, token order, fp32
__device__ __nv_bfloat16 g_hb[LTOK * HIDD];    // MLP hidden, bf16
__device__ __nv_bfloat16 g_bias6b[6 * 256 * 256];   // rel-pos bias, bf16
// transposed bf16 weights: [N, K] row-major
__device__ __nv_bfloat16 g_wqkv[576 * 192];
__device__ __nv_bfloat16 g_wproj[192 * 192];
__device__ __nv_bfloat16 g_wfc1[768 * 192];
__device__ __nv_bfloat16 g_wfc2[192 * 768];

// ---------------- mma.sync helpers ----------------
__device__ __forceinline__ u32 smem_u32(const void* p) {
    u32 a;
    asm("{ .reg .u64 t; cvta.to.shared.u64 t, %1; cvt.u32.u64 %0, t; }" : "=r"(a) : "l"(p));
    return a;
}
#define LDM4(R, addr)                                                            \
    asm volatile("ldmatrix.sync.aligned.m8n8.x4.shared.b16 {%0,%1,%2,%3}, [%4];" \
        : "=r"((R)[0]), "=r"((R)[1]), "=r"((R)[2]), "=r"((R)[3]) : "r"(addr))

#define LDM4T(R, addr)                                                           \
    asm volatile("ldmatrix.sync.aligned.m8n8.x4.trans.shared.b16 {%0,%1,%2,%3}, [%4];" \
        : "=r"((R)[0]), "=r"((R)[1]), "=r"((R)[2]), "=r"((R)[3]) : "r"(addr))

#define MMA(dd, A, B0, B1)                                                       \
    asm volatile("mma.sync.aligned.m16n8k16.row.col.f32.bf16.bf16.f32 "          \
        "{%0,%1,%2,%3}, {%4,%5,%6,%7}, {%8,%9}, {%0,%1,%2,%3};"                  \
        : "+f"((dd)[0]), "+f"((dd)[1]), "+f"((dd)[2]), "+f"((dd)[3])             \
        : "r"((A)[0]), "r"((A)[1]), "r"((A)[2]), "r"((A)[3]), "r"(B0), "r"(B1))

__device__ __forceinline__ u32 bfpack(float a, float b) {
    __nv_bfloat162 h = __floats2bfloat162_rn(a, b);
    return *(u32*)&h;
}

__device__ __forceinline__ float gelu_exact(float x) {
    return 0.5f * x * (1.0f + erff(x * 0.70710678118654752f));
}

// ============ coalesced tiled weight transpose: Wt[n*K+k] = W[k*N+n] ============
__global__ __launch_bounds__(256) void transw_tiled(const float* __restrict__ qkvw,
                                                    const float* __restrict__ projw,
                                                    const float* __restrict__ fc1w,
                                                    const float* __restrict__ fc2w) {
    __shared__ float t[32][33];
    int b = blockIdx.x;
    const float* W; __nv_bfloat16* Wt; int K, N, tb;
    if (b < 108)      { W = qkvw;  Wt = g_wqkv;  K = 192; N = 576; tb = b; }
    else if (b < 144) { W = projw; Wt = g_wproj; K = 192; N = 192; tb = b - 108; }
    else if (b < 288) { W = fc1w;  Wt = g_wfc1;  K = 192; N = 768; tb = b - 144; }
    else              { W = fc2w;  Wt = g_wfc2;  K = 768; N = 192; tb = b - 288; }
    int ntiles = N >> 5;
    int tr = tb / ntiles, tc = tb - tr * ntiles;   // k-tile, n-tile
    int tx = threadIdx.x & 31, ty = threadIdx.x >> 5;
#pragma unroll
    for (int rr = 0; rr < 4; rr++) {
        int k = tr * 32 + ty + rr * 8;
        t[ty + rr * 8][tx] = W[(size_t)k * N + tc * 32 + tx];
    }
    __syncthreads();
#pragma unroll
    for (int rr = 0; rr < 4; rr++) {
        int n = tc * 32 + ty + rr * 8;
        Wt[(size_t)n * K + tr * 32 + tx] = __float2bfloat16_rn(t[tx][ty + rr * 8]);
    }
}

// ============ relative position bias gather (bf16) ============
__global__ void bias6_kernel(const int* __restrict__ rpi, const float* __restrict__ rpb) {
    int id = blockIdx.x * 256 + threadIdx.x;
    int head = id >> 16;
    int nm = id & 65535;
    g_bias6b[id] = __float2bfloat16_rn(rpb[rpi[nm] * 6 + head]);
}

// ============ LayerNorm: warp-per-token, bf16 out ============
__global__ __launch_bounds__(256) void ln_kernel(const float* __restrict__ xin,
                                                 const float* __restrict__ gw,
                                                 const float* __restrict__ bw, int mode) {
    int gwid = (blockIdx.x * 256 + threadIdx.x) >> 5;
    int l = threadIdx.x & 31;
    int nwarp = (gridDim.x * 256) >> 5;

    float gg[6], bb[6];
#pragma unroll
    for (int j = 0; j < 6; j++) { gg[j] = gw[l + 32 * j]; bb[j] = bw[l + 32 * j]; }

    const float* src = mode ? xin : g_xr;
    for (int s = gwid; s < LTOK; s += nwarp) {
        const float* in = src + (size_t)s * CDIM;
        float v[6], sum = 0.0f, sq = 0.0f;
#pragma unroll
        for (int j = 0; j < 6; j++) {
            v[j] = in[l + 32 * j];
            sum += v[j];
            sq += v[j] * v[j];
        }
#pragma unroll
        for (int o = 16; o; o >>= 1) {
            sum += __shfl_xor_sync(0xffffffffu, sum, o);
            sq  += __shfl_xor_sync(0xffffffffu, sq, o);
        }
        float mean = sum * (1.0f / CDIM);
        float var = sq * (1.0f / CDIM) - mean * mean;
        float rs = rsqrtf(var + 1e-5f);
        int r;
        if (mode) {
            int h = s >> 8, w = s & 255;
            int i = (h + 248) & 255, j = (w + 248) & 255;
            r = (((i >> 4) << 4) + (j >> 4)) * 256 + ((i & 15) << 4) + (j & 15);
        } else {
            r = s;
        }
        __nv_bfloat16* dst = g_xwb + (size_t)r * CDIM;
#pragma unroll
        for (int j = 0; j < 6; j++)
            dst[l + 32 * j] = __float2bfloat16_rn((v[j] - mean) * rs * gg[j] + bb[j]);
    }
}

// ============ epilogue pair-store ============
template <int MODE>
__device__ __forceinline__ void store2(int r, int n, float2 v,
                                       const float* __restrict__ aux,
                                       float* __restrict__ outp) {
    if (MODE == 0) {
        int which = n / 192;
        int rem = n - which * 192;
        int head = rem >> 5, dd = rem & 31;
        int wnd = r >> 8, nn = r & 255;
        __nv_bfloat16* dst = ((which == 0) ? g_q : (which == 1) ? g_k : g_v)
                             + (size_t)((wnd * 6 + head) * 256 + nn) * 32 + dd;
        if (which == 0) {
            v.x *= 0.17677669529663687f;
            v.y *= 0.17677669529663687f;
        }
        *(u32*)dst = bfpack(v.x, v.y);
    } else if (MODE == 1) {
        int wnd = r >> 8, nn = r & 255;
        int i_ = ((wnd >> 4) << 4) + (nn >> 4);
        int j_ = ((wnd & 15) << 4) + (nn & 15);
        int s = (((i_ + 8) & 255) << 8) + ((j_ + 8) & 255);
        float2 a = *(const float2*)(aux + (size_t)s * CDIM + n);
        v.x += a.x; v.y += a.y;
        *(float2*)(g_xr + (size_t)s * CDIM + n) = v;
    } else if (MODE == 2) {
        *(u32*)(g_hb + (size_t)r * HIDD + n) = bfpack(gelu_exact(v.x), gelu_exact(v.y));
    } else {
        float2 a = *(const float2*)(g_xr + (size_t)r * CDIM + n);
        v.x += a.x; v.y += a.y;
        *(float2*)(outp + (size_t)r * CDIM + n) = v;
    }
}

// ============ A-resident GEMM for K=192, double-buffered B, 2 CTAs/SM ============
// A tile in smem (loaded once); a-frags re-ldmatrix'd per k-step (keeps regs <=124
// so TWO CTAs fit per SM -> sync/epilogue stalls of one CTA overlap the other's MMAs).
#define ARES_SMEM (128 * 400 + 2 * 64 * 400)
template <int MODE>
__global__ __launch_bounds__(256, 2) void tmmaA(const float* __restrict__ bias,
                                                const float* __restrict__ aux,
                                                float* __restrict__ outp, int NT) {
    extern __shared__ __align__(16) char sm[];
    char* As = sm;                       // 128 * 400
    char* Bs = sm + 128 * 400;           // 2 buffers * 64 * 400

    const __nv_bfloat16* Ag = (MODE == 1) ? g_aob : g_xwb;
    const __nv_bfloat16* Wt = (MODE == 0) ? g_wqkv : (MODE == 1) ? g_wproj : g_wfc1;

    int tid = threadIdx.x;
    int w = tid >> 5, l = tid & 31;
    int wm = w & 3, wn = w >> 2;
    int m0 = blockIdx.x * 128;

    // prefetch B tile 0
    uint4 pf[6];
#pragma unroll
    for (int j = 0; j < 6; j++) {
        int id = tid + j * 256;
        int row = id / 24, ch = id - row * 24;
        pf[j] = *(const uint4*)(Wt + (size_t)row * 192 + ch * 8);
    }
    // load A tile
#pragma unroll
    for (int j = 0; j < 12; j++) {
        int id = tid + j * 256;
        int row = id / 24, ch = id - row * 24;
        *(uint4*)(As + row * 400 + ch * 16) =
            *(const uint4*)(Ag + (size_t)(m0 + row) * 192 + ch * 8);
    }
    // store B tile 0 into buffer 0
#pragma unroll
    for (int j = 0; j < 6; j++) {
        int id = tid + j * 256;
        int row = id / 24, ch = id - row * 24;
        *(uint4*)(Bs + row * 400 + ch * 16) = pf[j];
    }
    __syncthreads();

    u32 sa = smem_u32(As), sb0 = smem_u32(Bs);
    u32 aBase0 = sa + (wm * 32 + (l & 15)) * 400 + (l >> 4) * 16;        // mt=0
    u32 aBase1 = aBase0 + 16 * 400;                                      // mt=1

    // prefetch tile 1
    if (NT > 1) {
        const __nv_bfloat16* Wn = Wt + (size_t)64 * 192;
#pragma unroll
        for (int j = 0; j < 6; j++) {
            int id = tid + j * 256;
            int row = id / 24, ch = id - row * 24;
            pf[j] = *(const uint4*)(Wn + (size_t)row * 192 + ch * 8);
        }
    }

    u32 bOff = (wn * 32 + (l & 7) + ((l >> 3) & 1) * 8) * 400 + (l >> 4) * 16;
    int lq = l >> 2, lr = l & 3;

    for (int nt = 0; nt < NT; nt++) {
        int cur = nt & 1;
        // 1. store prefetched tile nt+1 into alt buffer
        if (nt + 1 < NT) {
            char* Bn = Bs + (1 - cur) * 25600;
#pragma unroll
            for (int j = 0; j < 6; j++) {
                int id = tid + j * 256;
                int row = id / 24, ch = id - row * 24;
                *(uint4*)(Bn + row * 400 + ch * 16) = pf[j];
            }
        }
        // 2. prefetch tile nt+2
        if (nt + 2 < NT) {
            const __nv_bfloat16* Wn = Wt + (size_t)(nt + 2) * 64 * 192;
#pragma unroll
            for (int j = 0; j < 6; j++) {
                int id = tid + j * 256;
                int row = id / 24, ch = id - row * 24;
                pf[j] = *(const uint4*)(Wn + (size_t)row * 192 + ch * 8);
            }
        }
        // 3. MMAs on current buffer (a-frags reloaded per k-step; regs stay low)
        u32 bBase = sb0 + cur * 25600 + bOff;
        float d[2][4][4];
#pragma unroll
        for (int mt = 0; mt < 2; mt++)
#pragma unroll
            for (int nj = 0; nj < 4; nj++)
#pragma unroll
                for (int q = 0; q < 4; q++) d[mt][nj][q] = 0.0f;

#pragma unroll
        for (int ks = 0; ks < 12; ks++) {
            u32 a0[4], a1[4], r0[4], r1[4];
            LDM4(a0, aBase0 + ks * 32);
            LDM4(a1, aBase1 + ks * 32);
            LDM4(r0, bBase + ks * 32);
            LDM4(r1, bBase + 6400 + ks * 32);
            MMA(d[0][0], a0, r0[0], r0[2]);
            MMA(d[0][1], a0, r0[1], r0[3]);
            MMA(d[0][2], a0, r1[0], r1[2]);
            MMA(d[0][3], a0, r1[1], r1[3]);
            MMA(d[1][0], a1, r0[0], r0[2]);
            MMA(d[1][1], a1, r0[1], r0[3]);
            MMA(d[1][2], a1, r1[0], r1[2]);
            MMA(d[1][3], a1, r1[1], r1[3]);
        }
        // 4. epilogue
#pragma unroll
        for (int mt = 0; mt < 2; mt++) {
            int ra = m0 + wm * 32 + mt * 16 + lq;
            int rb = ra + 8;
#pragma unroll
            for (int nj = 0; nj < 4; nj++) {
                int ng = nt * 64 + wn * 32 + nj * 8 + lr * 2;
                float2 b2 = *(const float2*)(bias + ng);
                float2 v0 = make_float2(d[mt][nj][0] + b2.x, d[mt][nj][1] + b2.y);
                float2 v1 = make_float2(d[mt][nj][2] + b2.x, d[mt][nj][3] + b2.y);
                store2<MODE>(ra, ng, v0, aux, outp);
                store2<MODE>(rb, ng, v1, aux, outp);
            }
        }
        __syncthreads();
    }
}

// ============ fc2 GEMM: K=768, BM=128, BN=192 single pass, double-buffered ============
// layout: A0@0 (10240), B0@10240 (15360), A1@25600, B1@35840 ; total 51200
#define FC2_SMEM (2 * (128 * 80 + 192 * 80))
__global__ __launch_bounds__(256) void tmmaF(const float* __restrict__ bias,
                                             float* __restrict__ outp) {
    extern __shared__ __align__(16) char smF[];
    int tid = threadIdx.x;
    int w = tid >> 5, l = tid & 31;
    int wm = w & 3, wn = w >> 2;   // 4 x 2 warps; warp tile 32 x 96
    int m0 = blockIdx.x * 128;

    const __nv_bfloat16* Ag = g_hb;
    const __nv_bfloat16* Wt = g_wfc2;

    u32 s0 = smem_u32(smF);
    u32 aOff = (wm * 32 + (l & 7) + ((l >> 3) & 1) * 8) * 80 + (l >> 4) * 16;
    u32 bOff = 10240 + (wn * 96 + (l & 7) + ((l >> 3) & 1) * 8) * 80 + (l >> 4) * 16;

    float d[2][12][4];
#pragma unroll
    for (int mt = 0; mt < 2; mt++)
#pragma unroll
        for (int nj = 0; nj < 12; nj++)
#pragma unroll
            for (int q = 0; q < 4; q++) d[mt][nj][q] = 0.0f;

    uint4 pa[2], pb[3];
#pragma unroll
    for (int j = 0; j < 2; j++) {
        int id = tid + j * 256;
        pa[j] = *(const uint4*)(Ag + (size_t)(m0 + (id >> 2)) * HIDD + (id & 3) * 8);
    }
#pragma unroll
    for (int j = 0; j < 3; j++) {
        int id = tid + j * 256;
        pb[j] = *(const uint4*)(Wt + (size_t)(id >> 2) * HIDD + (id & 3) * 8);
    }
    // store k-slab 0 into buffer 0
#pragma unroll
    for (int j = 0; j < 2; j++) {
        int id = tid + j * 256;
        *(uint4*)(smF + (id >> 2) * 80 + (id & 3) * 16) = pa[j];
    }
#pragma unroll
    for (int j = 0; j < 3; j++) {
        int id = tid + j * 256;
        *(uint4*)(smF + 10240 + (id >> 2) * 80 + (id & 3) * 16) = pb[j];
    }
    __syncthreads();
    // prefetch slab 1
    {
#pragma unroll
        for (int j = 0; j < 2; j++) {
            int id = tid + j * 256;
            pa[j] = *(const uint4*)(Ag + (size_t)(m0 + (id >> 2)) * HIDD + 32 + (id & 3) * 8);
        }
#pragma unroll
        for (int j = 0; j < 3; j++) {
            int id = tid + j * 256;
            pb[j] = *(const uint4*)(Wt + (size_t)(id >> 2) * HIDD + 32 + (id & 3) * 8);
        }
    }

    for (int kt = 0; kt < 24; kt++) {
        int cur = kt & 1;
        // 1. store prefetched slab kt+1 into alt buffer
        if (kt + 1 < 24) {
            char* base = smF + (1 - cur) * 25600;
#pragma unroll
            for (int j = 0; j < 2; j++) {
                int id = tid + j * 256;
                *(uint4*)(base + (id >> 2) * 80 + (id & 3) * 16) = pa[j];
            }
#pragma unroll
            for (int j = 0; j < 3; j++) {
                int id = tid + j * 256;
                *(uint4*)(base + 10240 + (id >> 2) * 80 + (id & 3) * 16) = pb[j];
            }
        }
        // 2. prefetch slab kt+2
        if (kt + 2 < 24) {
            int kc = (kt + 2) * 32;
#pragma unroll
            for (int j = 0; j < 2; j++) {
                int id = tid + j * 256;
                pa[j] = *(const uint4*)(Ag + (size_t)(m0 + (id >> 2)) * HIDD + kc + (id & 3) * 8);
            }
#pragma unroll
            for (int j = 0; j < 3; j++) {
                int id = tid + j * 256;
                pb[j] = *(const uint4*)(Wt + (size_t)(id >> 2) * HIDD + kc + (id & 3) * 8);
            }
        }
        // 3. MMAs on current buffer
        u32 aBase = s0 + cur * 25600 + aOff;
        u32 bBase = s0 + cur * 25600 + bOff;
#pragma unroll
        for (int ks = 0; ks < 2; ks++) {
            u32 a0[4], a1[4];
            LDM4(a0, aBase + ks * 32);
            LDM4(a1, aBase + 1280 + ks * 32);
#pragma unroll
            for (int g = 0; g < 6; g++) {
                u32 rg[4];
                LDM4(rg, bBase + g * 1280 + ks * 32);
                MMA(d[0][2 * g],     a0, rg[0], rg[2]);
                MMA(d[0][2 * g + 1], a0, rg[1], rg[3]);
                MMA(d[1][2 * g],     a1, rg[0], rg[2]);
                MMA(d[1][2 * g + 1], a1, rg[1], rg[3]);
            }
        }
        __syncthreads();
    }

    int lq = l >> 2, lr = l & 3;
#pragma unroll
    for (int mt = 0; mt < 2; mt++) {
        int ra = m0 + wm * 32 + mt * 16 + lq;
        int rb = ra + 8;
#pragma unroll
        for (int nj = 0; nj < 12; nj++) {
            int ng = wn * 96 + nj * 8 + lr * 2;
            float2 b2 = *(const float2*)(bias + ng);
            float2 v0 = make_float2(d[mt][nj][0] + b2.x, d[mt][nj][1] + b2.y);
            float2 v1 = make_float2(d[mt][nj][2] + b2.x, d[mt][nj][3] + b2.y);
            store2<3>(ra, ng, v0, nullptr, outp);
            store2<3>(rb, ng, v1, nullptr, outp);
        }
    }
}

// ============ tensor-core attention: one block per (window, head) ============
// 8 warps, two 128-query passes; keys split into two 128-halves to cut registers
// (sum + unnormalized O accumulate across halves — identical math, no rescale).
#define ATT_SMEM (256 * 80 * 3)
__global__ __launch_bounds__(256, 2) void attn_mma(const float* __restrict__ mask) {
    extern __shared__ __align__(16) char sm[];
    char* Qs = sm;
    char* Ksm = sm + 256 * 80;
    char* Vsm = sm + 2 * 256 * 80;

    int bid = blockIdx.x;
    int wnd = bid / 6;
    int head = bid - wnd * 6;
    int tid = threadIdx.x;

    size_t gbase = (size_t)((wnd * 6 + head) * 256) * 32;
    const uint4* Qg = (const uint4*)(g_q + gbase);
    const uint4* Kg = (const uint4*)(g_k + gbase);
    const uint4* Vg = (const uint4*)(g_v + gbase);
    for (int i = tid; i < 1024; i += 256) {
        int row = i >> 2, c4 = i & 3;
        int off = row * 80 + c4 * 16;
        *(uint4*)(Qs + off)  = Qg[i];
        *(uint4*)(Ksm + off) = Kg[i];
        *(uint4*)(Vsm + off) = Vg[i];
    }
    __syncthreads();

    int w = tid >> 5, l = tid & 31;
    u32 sQ = smem_u32(Qs), sK = smem_u32(Ksm), sV = smem_u32(Vsm);
    bool border = ((wnd >> 4) == 15) || ((wnd & 15) == 15);

#pragma unroll 1
    for (int hh = 0; hh < 2; hh++) {
        int qr = hh * 128 + w * 16;
        u32 qa[8];
        LDM4(qa,     sQ + (qr + (l & 15)) * 80 + (l >> 4) * 16);
        LDM4(qa + 4, sQ + (qr + (l & 15)) * 80 + 32 + (l >> 4) * 16);

        int r0 = qr + (l >> 2);
        const __nv_bfloat16* bA = g_bias6b + head * 65536 + r0 * 256;
        const __nv_bfloat16* bB = bA + 2048;
        const float* mA = mask + (size_t)wnd * 65536 + r0 * 256;
        const float* mB = mA + 2048;

        float sA = 0.0f, sB = 0.0f;
        float o[4][4];
#pragma unroll
        for (int nt = 0; nt < 4; nt++)
#pragma unroll
            for (int q = 0; q < 4; q++) o[nt][q] = 0.0f;

#pragma unroll 1
        for (int kh = 0; kh < 2; kh++) {
            int kb0 = kh * 128;
            float d[16][4];
#pragma unroll
            for (int t = 0; t < 16; t++)
#pragma unroll
                for (int q = 0; q < 4; q++) d[t][q] = 0.0f;

#pragma unroll
            for (int t = 0; t < 16; t++) {
                u32 kb[4];
                LDM4(kb, sK + (kb0 + t * 8 + (l & 7)) * 80 + (l >> 3) * 16);
                MMA(d[t], qa, kb[0], kb[1]);
                MMA(d[t], qa + 4, kb[2], kb[3]);
            }

            u32 pbf[8][4];
#pragma unroll
            for (int t = 0; t < 16; t++) {
                int c = kb0 + t * 8 + 2 * (l & 3);
                float2 aA = __bfloat1622float2(*(const __nv_bfloat162*)(bA + c));
                float2 aB = __bfloat1622float2(*(const __nv_bfloat162*)(bB + c));
                if (border) {
                    float2 ma = *(const float2*)(mA + c);
                    float2 mb = *(const float2*)(mB + c);
                    aA.x += ma.x; aA.y += ma.y;
                    aB.x += mb.x; aB.y += mb.y;
                }
                float p0 = __expf(d[t][0] + aA.x);
                float p1 = __expf(d[t][1] + aA.y);
                float p2 = __expf(d[t][2] + aB.x);
                float p3 = __expf(d[t][3] + aB.y);
                sA += p0 + p1;
                sB += p2 + p3;
                int kt = t >> 1, s4 = (t & 1) * 2;
                pbf[kt][s4]     = bfpack(p0, p1);
                pbf[kt][s4 + 1] = bfpack(p2, p3);
            }

#pragma unroll
            for (int kt = 0; kt < 8; kt++) {
                u32 v0[4], v1[4];
                u32 vaddr = sV + (kb0 + kt * 16 + (l & 7) + ((l >> 3) & 1) * 8) * 80 + (l >> 4) * 16;
                LDM4T(v0, vaddr);
                LDM4T(v1, vaddr + 32);
                MMA(o[0], pbf[kt], v0[0], v0[1]);
                MMA(o[1], pbf[kt], v0[2], v0[3]);
                MMA(o[2], pbf[kt], v1[0], v1[1]);
                MMA(o[3], pbf[kt], v1[2], v1[3]);
            }
        }

        sA += __shfl_xor_sync(0xffffffffu, sA, 1);
        sA += __shfl_xor_sync(0xffffffffu, sA, 2);
        sB += __shfl_xor_sync(0xffffffffu, sB, 1);
        sB += __shfl_xor_sync(0xffffffffu, sB, 2);
        float invA = 1.0f / sA, invB = 1.0f / sB;

        __nv_bfloat16* OA = g_aob + (size_t)(wnd * 256 + r0) * CDIM + head * 32;
        __nv_bfloat16* OB = OA + (size_t)8 * CDIM;
#pragma unroll
        for (int nt = 0; nt < 4; nt++) {
            int c = nt * 8 + 2 * (l & 3);
            *(u32*)(OA + c) = bfpack(o[nt][0] * invA, o[nt][1] * invA);
            *(u32*)(OB + c) = bfpack(o[nt][2] * invB, o[nt][3] * invB);
        }
    }
}

// ============ host launcher ============
extern "C" void kernel_launch(void* const* d_in, const int* in_sizes, int n_in,
                              void* d_out, int out_size) {
    const float* x     = (const float*)d_in[0];
    const int*   rpi   = (const int*)d_in[1];
    const float* mask  = (const float*)d_in[2];
    const float* n1g   = (const float*)d_in[3];
    const float* n1b   = (const float*)d_in[4];
    const float* qkvw  = (const float*)d_in[5];
    const float* qkvb  = (const float*)d_in[6];
    const float* rpb   = (const float*)d_in[7];
    const float* projw = (const float*)d_in[8];
    const float* projb = (const float*)d_in[9];
    const float* n2g   = (const float*)d_in[10];
    const float* n2b   = (const float*)d_in[11];
    const float* fc1w  = (const float*)d_in[12];
    const float* fc1b  = (const float*)d_in[13];
    const float* fc2w  = (const float*)d_in[14];
    const float* fc2b  = (const float*)d_in[15];
    float* out = (float*)d_out;

    cudaFuncSetAttribute(attn_mma, cudaFuncAttributeMaxDynamicSharedMemorySize, ATT_SMEM);
    cudaFuncSetAttribute(tmmaA<0>, cudaFuncAttributeMaxDynamicSharedMemorySize, ARES_SMEM);
    cudaFuncSetAttribute(tmmaA<1>, cudaFuncAttributeMaxDynamicSharedMemorySize, ARES_SMEM);
    cudaFuncSetAttribute(tmmaA<2>, cudaFuncAttributeMaxDynamicSharedMemorySize, ARES_SMEM);
    cudaFuncSetAttribute(tmmaF, cudaFuncAttributeMaxDynamicSharedMemorySize, FC2_SMEM);

    transw_tiled<<<432, 256>>>(qkvw, projw, fc1w, fc2w);
    bias6_kernel<<<1536, 256>>>(rpi, rpb);

    ln_kernel<<<592, 256>>>(x, n1g, n1b, 1);                            // LN1 + shift + partition
    tmmaA<0><<<512, 256, ARES_SMEM>>>(qkvb, nullptr, nullptr, 9);       // QKV -> q/k/v bf16
    attn_mma<<<1536, 256, ATT_SMEM>>>(mask);                            // attention -> g_aob
    tmmaA<1><<<512, 256, ARES_SMEM>>>(projb, x, nullptr, 3);            // proj + reverse + resid
    ln_kernel<<<592, 256>>>(x, n2g, n2b, 0);                            // LN2 (reads g_xr)
    tmmaA<2><<<512, 256, ARES_SMEM>>>(fc1b, nullptr, nullptr, 12);      // fc1 + GELU -> g_hb
    tmmaF<<<512, 256, FC2_SMEM>>>(fc2b, out);                           // fc2 + resid -> out
}